// round 1
// baseline (speedup 1.0000x reference)
#include <cuda_runtime.h>
#include <cstdint>

#define LQ 43054
#define D  256
#define NH 8
#define NL 4
#define NP 4
#define HD 32

// ---------------- scratch (device globals; no allocation allowed) ----------------
__device__ float g_q   [LQ * D];   // query + pos
__device__ float g_val [LQ * D];   // value projection
__device__ float g_off [LQ * 256]; // sampling offsets
__device__ float g_lgt [LQ * 128]; // attention logits
__device__ float g_acc [LQ * D];   // deformable attention output (pre w_out)
__device__ float g_x   [LQ * D];   // after LN1
__device__ float g_h   [LQ * D];   // FFN hidden
__device__ float g_f   [LQ * D];   // generic matmul output (attn_out, then ffn out)

// ---------------- elementwise add (float4) ----------------
__global__ void add_kernel(const float* __restrict__ a, const float* __restrict__ b,
                           float* __restrict__ c, int n4) {
    int i = blockIdx.x * blockDim.x + threadIdx.x;
    if (i >= n4) return;
    float4 va = reinterpret_cast<const float4*>(a)[i];
    float4 vb = reinterpret_cast<const float4*>(b)[i];
    float4 vc;
    vc.x = va.x + vb.x; vc.y = va.y + vb.y; vc.z = va.z + vb.z; vc.w = va.w + vb.w;
    reinterpret_cast<float4*>(c)[i] = vc;
}

// ---------------- SIMT fp32 GEMM: C[M,N] = A[M,256] @ B[256,N] + bias, opt ReLU ----
// BM=BN=128, BK=8, 256 threads, 8x8 per thread.
__global__ __launch_bounds__(256)
void sgemm128(const float* __restrict__ A, const float* __restrict__ B,
              const float* __restrict__ bias, float* __restrict__ C,
              int M, int N, int relu) {
    constexpr int K = 256;
    __shared__ float As[8][128];
    __shared__ float Bs[8][128];

    int tid = threadIdx.x;
    int bm = blockIdx.y * 128;
    int bn = blockIdx.x * 128;
    int tx = tid & 15;   // col group
    int ty = tid >> 4;   // row group

    float acc[8][8];
    #pragma unroll
    for (int i = 0; i < 8; i++)
        #pragma unroll
        for (int j = 0; j < 8; j++) acc[i][j] = 0.f;

    int a_row = tid >> 1;          // 0..127
    int a_col = (tid & 1) * 4;     // 0 or 4
    int b_row = tid >> 5;          // 0..7
    int b_col = (tid & 31) * 4;    // 0..124

    for (int k0 = 0; k0 < K; k0 += 8) {
        float4 av = make_float4(0.f, 0.f, 0.f, 0.f);
        int gr = bm + a_row;
        if (gr < M)
            av = *reinterpret_cast<const float4*>(A + (size_t)gr * K + k0 + a_col);
        As[a_col + 0][a_row] = av.x;
        As[a_col + 1][a_row] = av.y;
        As[a_col + 2][a_row] = av.z;
        As[a_col + 3][a_row] = av.w;

        float4 bv = *reinterpret_cast<const float4*>(B + (size_t)(k0 + b_row) * N + bn + b_col);
        *reinterpret_cast<float4*>(&Bs[b_row][b_col]) = bv;
        __syncthreads();

        #pragma unroll
        for (int k = 0; k < 8; k++) {
            float ra[8], rb[8];
            float4 a0 = *reinterpret_cast<const float4*>(&As[k][ty * 8]);
            float4 a1 = *reinterpret_cast<const float4*>(&As[k][ty * 8 + 4]);
            ra[0]=a0.x; ra[1]=a0.y; ra[2]=a0.z; ra[3]=a0.w;
            ra[4]=a1.x; ra[5]=a1.y; ra[6]=a1.z; ra[7]=a1.w;
            float4 b0 = *reinterpret_cast<const float4*>(&Bs[k][tx * 8]);
            float4 b1 = *reinterpret_cast<const float4*>(&Bs[k][tx * 8 + 4]);
            rb[0]=b0.x; rb[1]=b0.y; rb[2]=b0.z; rb[3]=b0.w;
            rb[4]=b1.x; rb[5]=b1.y; rb[6]=b1.z; rb[7]=b1.w;
            #pragma unroll
            for (int i = 0; i < 8; i++)
                #pragma unroll
                for (int j = 0; j < 8; j++)
                    acc[i][j] += ra[i] * rb[j];
        }
        __syncthreads();
    }

    #pragma unroll
    for (int i = 0; i < 8; i++) {
        int gr = bm + ty * 8 + i;
        if (gr >= M) continue;
        #pragma unroll
        for (int j0 = 0; j0 < 8; j0 += 4) {
            int gc = bn + tx * 8 + j0;
            float4 v;
            v.x = acc[i][j0 + 0] + bias[gc + 0];
            v.y = acc[i][j0 + 1] + bias[gc + 1];
            v.z = acc[i][j0 + 2] + bias[gc + 2];
            v.w = acc[i][j0 + 3] + bias[gc + 3];
            if (relu) {
                v.x = fmaxf(v.x, 0.f); v.y = fmaxf(v.y, 0.f);
                v.z = fmaxf(v.z, 0.f); v.w = fmaxf(v.w, 0.f);
            }
            *reinterpret_cast<float4*>(C + (size_t)gr * N + gc) = v;
        }
    }
}

// ---------------- deformable sampling + softmax ----------------
// block = one query (lq), warp = one head, lane = channel d (0..31)
__global__ __launch_bounds__(256)
void sample_kernel(const float* __restrict__ val,    // (LQ, 256) value projection
                   const float* __restrict__ refp,   // (LQ, NL, 2)
                   const float* __restrict__ off,    // (LQ, 256)
                   const float* __restrict__ lgt,    // (LQ, 128)
                   const int* __restrict__ shapes,   // (NL, 2) [H, W]
                   const int* __restrict__ starts,   // (NL,)
                   float* __restrict__ acc) {
    int lq = blockIdx.x;
    int h  = threadIdx.x >> 5;
    int lane = threadIdx.x & 31;

    // softmax over 16 (redundant across lanes; small)
    const float* lg = lgt + (size_t)lq * 128 + h * 16;
    float w[16];
    float mx = -1e30f;
    #pragma unroll
    for (int i = 0; i < 16; i++) { w[i] = lg[i]; mx = fmaxf(mx, w[i]); }
    float sum = 0.f;
    #pragma unroll
    for (int i = 0; i < 16; i++) { w[i] = expf(w[i] - mx); sum += w[i]; }
    float inv = 1.f / sum;

    const float* op = off + (size_t)lq * 256 + h * 32; // (l, p, 2)
    float a = 0.f;

    #pragma unroll
    for (int l = 0; l < NL; l++) {
        int Hl = shapes[l * 2 + 0];
        int Wl = shapes[l * 2 + 1];
        int st = starts[l];
        float rx = refp[(size_t)lq * 8 + l * 2 + 0];
        float ry = refp[(size_t)lq * 8 + l * 2 + 1];
        float fW = (float)Wl, fH = (float)Hl;
        #pragma unroll
        for (int p = 0; p < NP; p++) {
            float ox = op[(l * NP + p) * 2 + 0];
            float oy = op[(l * NP + p) * 2 + 1];
            float x = (rx + ox / fW) * fW - 0.5f;
            float y = (ry + oy / fH) * fH - 0.5f;
            float x0f = floorf(x), y0f = floorf(y);
            float fx = x - x0f, fy = y - y0f;
            int x0 = (int)x0f, y0 = (int)y0f;
            float s = 0.f;
            #pragma unroll
            for (int dy = 0; dy < 2; dy++) {
                #pragma unroll
                for (int dx = 0; dx < 2; dx++) {
                    int xi = x0 + dx, yi = y0 + dy;
                    if (xi >= 0 && xi < Wl && yi >= 0 && yi < Hl) {
                        float wt = (dx ? fx : 1.f - fx) * (dy ? fy : 1.f - fy);
                        const float* vp = val + ((size_t)(st + yi * Wl + xi) * 256 + h * 32);
                        s += wt * vp[lane];
                    }
                }
            }
            a += w[l * NP + p] * s;
        }
    }
    acc[(size_t)lq * 256 + h * 32 + lane] = a * inv;
}

// ---------------- fused residual + LayerNorm (warp per row) ----------------
__global__ __launch_bounds__(256)
void ln_kernel(const float* __restrict__ res, const float* __restrict__ y,
               const float* __restrict__ g, const float* __restrict__ b,
               float* __restrict__ out, int M) {
    int warp = (blockIdx.x * blockDim.x + threadIdx.x) >> 5;
    int lane = threadIdx.x & 31;
    if (warp >= M) return;
    const float* r  = res + (size_t)warp * 256;
    const float* yy = y   + (size_t)warp * 256;
    float v[8];
    float s = 0.f;
    #pragma unroll
    for (int i = 0; i < 8; i++) {
        v[i] = r[lane + 32 * i] + yy[lane + 32 * i];
        s += v[i];
    }
    #pragma unroll
    for (int o = 16; o; o >>= 1) s += __shfl_xor_sync(0xffffffffu, s, o);
    float m = s * (1.f / 256.f);
    float vs = 0.f;
    #pragma unroll
    for (int i = 0; i < 8; i++) { float d = v[i] - m; vs += d * d; }
    #pragma unroll
    for (int o = 16; o; o >>= 1) vs += __shfl_xor_sync(0xffffffffu, vs, o);
    float rs = rsqrtf(vs * (1.f / 256.f) + 1e-5f);
    #pragma unroll
    for (int i = 0; i < 8; i++) {
        int c = lane + 32 * i;
        out[(size_t)warp * 256 + c] = (v[i] - m) * rs * g[c] + b[c];
    }
}

// ---------------- host ----------------
extern "C" void kernel_launch(void* const* d_in, const int* in_sizes, int n_in,
                              void* d_out, int out_size) {
    const float* query = (const float*)d_in[0];
    const float* refp  = (const float*)d_in[1];
    const float* pos   = (const float*)d_in[2];
    const int*   shp   = (const int*)d_in[3];
    const int*   sti   = (const int*)d_in[4];
    const float* w_off = (const float*)d_in[5];
    const float* b_off = (const float*)d_in[6];
    const float* w_attn= (const float*)d_in[7];
    const float* b_attn= (const float*)d_in[8];
    const float* w_val = (const float*)d_in[9];
    const float* b_val = (const float*)d_in[10];
    const float* w_out = (const float*)d_in[11];
    const float* b_out = (const float*)d_in[12];
    const float* g1    = (const float*)d_in[13];
    const float* be1   = (const float*)d_in[14];
    const float* w1    = (const float*)d_in[15];
    const float* b1    = (const float*)d_in[16];
    const float* w2    = (const float*)d_in[17];
    const float* b2    = (const float*)d_in[18];
    const float* g2    = (const float*)d_in[19];
    const float* be2   = (const float*)d_in[20];
    float* out = (float*)d_out;

    float *q, *val, *off, *lgt, *acc, *x, *h, *f;
    cudaGetSymbolAddress((void**)&q,   g_q);
    cudaGetSymbolAddress((void**)&val, g_val);
    cudaGetSymbolAddress((void**)&off, g_off);
    cudaGetSymbolAddress((void**)&lgt, g_lgt);
    cudaGetSymbolAddress((void**)&acc, g_acc);
    cudaGetSymbolAddress((void**)&x,   g_x);
    cudaGetSymbolAddress((void**)&h,   g_h);
    cudaGetSymbolAddress((void**)&f,   g_f);

    const int M = LQ;
    dim3 gemm_grid_256(2, (M + 127) / 128);
    dim3 gemm_grid_128(1, (M + 127) / 128);

    // q = query + pos
    {
        int n4 = (LQ * D) / 4;
        add_kernel<<<(n4 + 255) / 256, 256>>>(query, pos, q, n4);
    }
    // value = query @ w_val + b_val
    sgemm128<<<gemm_grid_256, 256>>>(query, w_val, b_val, val, M, 256, 0);
    // off = q @ w_off + b_off
    sgemm128<<<gemm_grid_256, 256>>>(q, w_off, b_off, off, M, 256, 0);
    // logits = q @ w_attn + b_attn
    sgemm128<<<gemm_grid_128, 256>>>(q, w_attn, b_attn, lgt, M, 128, 0);
    // deformable sampling (softmax fused)
    sample_kernel<<<LQ, 256>>>(val, refp, off, lgt, shp, sti, acc);
    // attn_out = acc @ w_out + b_out   -> f
    sgemm128<<<gemm_grid_256, 256>>>(acc, w_out, b_out, f, M, 256, 0);
    // x = LN(query + attn_out)
    {
        int blocks = (M * 32 + 255) / 256;
        ln_kernel<<<blocks, 256>>>(query, f, g1, be1, x, M);
    }
    // h = relu(x @ w1 + b1)
    sgemm128<<<gemm_grid_256, 256>>>(x, w1, b1, h, M, 256, 1);
    // f = h @ w2 + b2
    sgemm128<<<gemm_grid_256, 256>>>(h, w2, b2, f, M, 256, 0);
    // out = LN(x + f)
    {
        int blocks = (M * 32 + 255) / 256;
        ln_kernel<<<blocks, 256>>>(x, f, g2, be2, out, M);
    }
}